// round 8
// baseline (speedup 1.0000x reference)
#include <cuda_runtime.h>

#define C_    16
#define H_    512
#define W_    512
#define HW_   (H_ * W_)
#define HID_  128
#define FEAT_ 80
#define NSTEP 8
#define MT    128           // pixels per block tile
#define NTHR  256
#define HSTRIDE 132         // Hs row stride (floats): 16B-aligned, conflict-breaking

__device__ float g_buf[2][C_ * HW_];

typedef unsigned long long u64;

__device__ __forceinline__ u64 pack2(float lo, float hi) {
    u64 r; asm("mov.b64 %0, {%1, %2};" : "=l"(r) : "f"(lo), "f"(hi)); return r;
}
__device__ __forceinline__ void unpack2(u64 v, float& lo, float& hi) {
    asm("mov.b64 {%0, %1}, %2;" : "=f"(lo), "=f"(hi) : "l"(v));
}
__device__ __forceinline__ u64 ffma2(u64 a, u64 b, u64 c) {
    u64 d; asm("fma.rn.f32x2 %0, %1, %2, %3;" : "=l"(d) : "l"(a), "l"(b), "l"(c)); return d;
}
__device__ __forceinline__ u64 relu2(u64 v) {
    float lo, hi; unpack2(v, lo, hi);
    return pack2(fmaxf(lo, 0.f), fmaxf(hi, 0.f));
}

// smem layout (bytes):
//   As  [80][128] f32          @ 0       (40960)
//   W1d [80][128] u64 dup'd    @ 40960   (81920)
//   Hs  [128][HSTRIDE] f32     @ 122880  (67584)
//   W2d [128][16] u64 dup'd    @ 190464  (16384)
#define SMEM_BYTES 206848

__global__ __launch_bounds__(NTHR, 1)
void slime_step(const float* __restrict__ src, float* __restrict__ dst,
                const float* __restrict__ gW1, const float* __restrict__ gb1,
                const float* __restrict__ gW2, const float* __restrict__ gb2)
{
    extern __shared__ char smraw[];
    float* As  = (float*)smraw;                 // [k][m]
    u64*   W1d = (u64*)(smraw + 40960);         // [k][n] dup'd pairs
    float* Hs  = (float*)(smraw + 122880);      // [j][HSTRIDE]
    u64*   W2d = (u64*)(smraw + 190464);        // [j][c] dup'd pairs

    const int tid = threadIdx.x;

    // ---- fill weight tiles (dup'd pairs) ----
    for (int i = tid; i < FEAT_ * HID_; i += NTHR) { const float w = gW1[i]; W1d[i] = pack2(w, w); }
    for (int i = tid; i < HID_ * C_;  i += NTHR)   { const float w = gW2[i]; W2d[i] = pack2(w, w); }

    // ---- gather feature tile A[k][m] ----
    const int pbase = blockIdx.x * MT;          // 128 pixels, all in one row
    const int y  = pbase >> 9;
    const int xb = pbase & (W_ - 1);
    const int yu = (y == 0)      ? 0 : y - 1;   // minus: clamp
    const int yd = (y == H_ - 1) ? 0 : y + 1;   // plus: WRAP (reference quirk)
    const int rc = y * W_, ru = yu * W_, rd = yd * W_;

    for (int i = tid; i < FEAT_ * MT; i += NTHR) {
        const int k = i >> 7, m = i & (MT - 1);
        const int nb = k >> 4, c = k & (C_ - 1);
        const int x = xb + m;
        int idx;
        if      (nb == 0) idx = rc + x;
        else if (nb == 1) idx = ru + x;
        else if (nb == 2) idx = rd + x;
        else if (nb == 3) idx = rc + ((x == 0)      ? 0 : x - 1);
        else              idx = rc + ((x == W_ - 1) ? 0 : x + 1);
        As[k * MT + m] = src[c * HW_ + idx];
    }
    __syncthreads();

    // ---- GEMM1: H[128m][128n] = A[128m][80k] @ W1[80k][128n], relu ----
    // thread (tm, tn): m = tm*8 .. +7 (4 f32x2 pairs), n = ng*32 + tn*2 + q
    const int tm = tid >> 4;        // 0..15
    const int tn = tid & 15;        // 0..15

    u64 acc[4][8];                  // [m-pair][ng*2+q]
#pragma unroll
    for (int ng = 0; ng < 4; ng++)
#pragma unroll
        for (int q = 0; q < 2; q++) {
            const float b = __ldg(&gb1[ng * 32 + tn * 2 + q]);
            const u64 bb = pack2(b, b);
#pragma unroll
            for (int mp = 0; mp < 4; mp++) acc[mp][ng * 2 + q] = bb;
        }

    const float* arow = As + tm * 8;
    const u64*   brow = W1d + tn * 2;
#pragma unroll 8
    for (int k = 0; k < FEAT_; k++) {
        const ulonglong2 a01 = *(const ulonglong2*)(arow + k * MT);        // pairs (m0,m1),(m2,m3)
        const ulonglong2 a23 = *(const ulonglong2*)(arow + k * MT + 4);    // pairs (m4,m5),(m6,m7)
        const u64 a[4] = { a01.x, a01.y, a23.x, a23.y };
        u64 b[8];
#pragma unroll
        for (int ng = 0; ng < 4; ng++) {
            const ulonglong2 bv = *(const ulonglong2*)(brow + k * HID_ + ng * 32);
            b[ng * 2]     = bv.x;
            b[ng * 2 + 1] = bv.y;
        }
#pragma unroll
        for (int mp = 0; mp < 4; mp++)
#pragma unroll
            for (int n = 0; n < 8; n++)
                acc[mp][n] = ffma2(a[mp], b[n], acc[mp][n]);
    }

    // relu + store H[j][m]
#pragma unroll
    for (int ng = 0; ng < 4; ng++)
#pragma unroll
        for (int q = 0; q < 2; q++) {
            const int j = ng * 32 + tn * 2 + q;
#pragma unroll
            for (int mp = 0; mp < 4; mp++)
                *(u64*)&Hs[j * HSTRIDE + tm * 8 + 2 * mp] = relu2(acc[mp][q + ng * 2]);
        }
    __syncthreads();

    // ---- GEMM2: D[128m][16c] = relu(H)[128m][128j] @ W2[128j][16c] ----
    // thread: m4 = tid/8 (4 m's), tc = tid%8 (2 c's)
    const int m4 = tid >> 3;        // 0..31
    const int tc = tid & 7;         // 0..7

    u64 dac[2][2];                  // [m-pair][ci]
#pragma unroll
    for (int ci = 0; ci < 2; ci++) {
        const float b = __ldg(&gb2[tc * 2 + ci]);
        dac[0][ci] = pack2(b, b);
        dac[1][ci] = pack2(b, b);
    }

    const float* hrow  = Hs + m4 * 4;
    const u64*   w2row = W2d + tc * 2;
#pragma unroll 8
    for (int j = 0; j < HID_; j++) {
        const ulonglong2 h = *(const ulonglong2*)(hrow + j * HSTRIDE);  // (m0,m1),(m2,m3)
        const ulonglong2 w = *(const ulonglong2*)(w2row + j * C_);      // dup'd c0, c1
        dac[0][0] = ffma2(h.x, w.x, dac[0][0]);
        dac[1][0] = ffma2(h.y, w.x, dac[1][0]);
        dac[0][1] = ffma2(h.x, w.y, dac[0][1]);
        dac[1][1] = ffma2(h.y, w.y, dac[1][1]);
    }

    // ---- epilogue: out = s + delta, channel 0 snapshot restore ----
#pragma unroll
    for (int ci = 0; ci < 2; ci++) {
        const int c = tc * 2 + ci;
#pragma unroll
        for (int mp = 0; mp < 2; mp++) {
            const int m0 = m4 * 4 + mp * 2;
            if (c == 0) {
                dst[pbase + m0]     = As[m0];
                dst[pbase + m0 + 1] = As[m0 + 1];
            } else {
                float d0, d1; unpack2(dac[mp][ci], d0, d1);
                dst[c * HW_ + pbase + m0]     = As[c * MT + m0]     + d0;
                dst[c * HW_ + pbase + m0 + 1] = As[c * MT + m0 + 1] + d1;
            }
        }
    }
}

extern "C" void kernel_launch(void* const* d_in, const int* in_sizes, int n_in,
                              void* d_out, int out_size)
{
    const float* state = (const float*)d_in[0];
    const float* W1    = (const float*)d_in[1];
    const float* b1    = (const float*)d_in[2];
    const float* W2    = (const float*)d_in[3];
    const float* b2    = (const float*)d_in[4];
    float* out = (float*)d_out;

    void* sym = nullptr;
    cudaGetSymbolAddress(&sym, g_buf);
    float* buf0 = (float*)sym;
    float* buf1 = buf0 + C_ * HW_;

    cudaFuncSetAttribute(slime_step, cudaFuncAttributeMaxDynamicSharedMemorySize, SMEM_BYTES);

    const float* src = state;
    for (int s = 0; s < NSTEP; s++) {
        float* dst = (s == NSTEP - 1) ? out : ((s & 1) ? buf1 : buf0);
        slime_step<<<HW_ / MT, NTHR, SMEM_BYTES>>>(src, dst, W1, b1, W2, b2);
        src = dst;
    }
}